// round 3
// baseline (speedup 1.0000x reference)
#include <cuda_runtime.h>
#include <cstdint>

#define N_NODES 50000
#define N_EDGES 200000
#define DIM     384
#define NREL    2

#define BM 64
#define BN 64
#define BK 16

// ---------------- device scratch (no runtime allocation allowed) ----------------
__device__ __align__(16) float g_xr[(size_t)NREL * N_NODES * DIM]; // per-relation transformed feats
__device__ __align__(16) float g_h1[(size_t)N_NODES * DIM];        // layer1 output
__device__ __align__(16) float g_h2[(size_t)N_NODES * DIM];        // layer2 output
__device__ int   g_cnt[N_NODES * NREL];   // in-degree per (node, relation)
__device__ int   g_srcoff[N_EDGES];       // r*N*D + src*D
__device__ int   g_dstoff[N_EDGES];       // dst*D
__device__ float g_scale[N_EDGES];        // 1/max(cnt[dst,r],1)

// ---------------- edge preprocessing (edge_index / edge_type are int32) ----------------
__global__ void zero_cnt_kernel() {
    int i = blockIdx.x * blockDim.x + threadIdx.x;
    if (i < N_NODES * NREL) g_cnt[i] = 0;
}

__device__ __forceinline__ int clampi(int v, int hi) {
    v = v < 0 ? 0 : v;
    return v >= hi ? hi - 1 : v;
}

__global__ void count_kernel(const int* __restrict__ ei,
                             const int* __restrict__ et) {
    int e = blockIdx.x * blockDim.x + threadIdx.x;
    if (e >= N_EDGES) return;
    int dst = clampi(ei[N_EDGES + e], N_NODES);
    int r   = clampi(et[e], NREL);
    atomicAdd(&g_cnt[dst * NREL + r], 1);
}

__global__ void build_edge_kernel(const int* __restrict__ ei,
                                  const int* __restrict__ et) {
    int e = blockIdx.x * blockDim.x + threadIdx.x;
    if (e >= N_EDGES) return;
    int src = clampi(ei[e], N_NODES);
    int dst = clampi(ei[N_EDGES + e], N_NODES);
    int r   = clampi(et[e], NREL);
    g_srcoff[e] = r * (N_NODES * DIM) + src * DIM;
    g_dstoff[e] = dst * DIM;
    int c = g_cnt[dst * NREL + r];
    g_scale[e] = 1.0f / (float)(c > 0 ? c : 1);
}

// ---------------- GEMM: C = relu_in(A) @ B (+bias on z==0) ----------------
// A selected by a_sel: 0 = Aext (embeddings), 1 = g_h1, 2 = g_h2.
// blockIdx.z: 0 -> root weight, output to {g_h1,g_h2,dout} per out_sel (with bias)
//             1 -> W[0], output to g_xr[0];  2 -> W[1], output to g_xr[1]
__global__ __launch_bounds__(256) void gemm3_kernel(
    const float* __restrict__ Aext, int a_sel,
    const float* __restrict__ Wroot, const float* __restrict__ Wrel,
    const float* __restrict__ bias,
    float* __restrict__ dout, int out_sel, int relu_in)
{
    const float* A = (a_sel == 0) ? Aext : (a_sel == 1) ? g_h1 : g_h2;
    const float* B;
    float* C;
    bool has_bias = false;
    if (blockIdx.z == 0) {
        B = Wroot;
        C = (out_sel == 0) ? g_h1 : (out_sel == 1) ? g_h2 : dout;
        has_bias = true;
    } else {
        B = Wrel + (size_t)(blockIdx.z - 1) * DIM * DIM;
        C = g_xr + (size_t)(blockIdx.z - 1) * N_NODES * DIM;
    }

    __shared__ float As[BK][BM + 4];
    __shared__ float Bs[BK][BN + 4];

    int tid = threadIdx.x;
    int tx = tid & 15;         // 0..15 -> output cols (x4)
    int ty = tid >> 4;         // 0..15 -> output rows (x4)
    int row0 = blockIdx.x * BM;
    int col0 = blockIdx.y * BN;

    float acc[4][4];
#pragma unroll
    for (int i = 0; i < 4; i++)
#pragma unroll
        for (int j = 0; j < 4; j++) acc[i][j] = 0.0f;

    // loader indexing
    int ar  = tid >> 2;          // 0..63
    int ac4 = (tid & 3) * 4;     // 0,4,8,12
    int br  = tid >> 4;          // 0..15
    int bc4 = (tid & 15) * 4;    // 0..60

    for (int k0 = 0; k0 < DIM; k0 += BK) {
        // A tile: [64 rows][16 cols], transposed into As[k][m]
        float4 av = make_float4(0.f, 0.f, 0.f, 0.f);
        int grow = row0 + ar;
        if (grow < N_NODES)
            av = *(const float4*)(A + (size_t)grow * DIM + k0 + ac4);
        if (relu_in) {
            av.x = fmaxf(av.x, 0.f); av.y = fmaxf(av.y, 0.f);
            av.z = fmaxf(av.z, 0.f); av.w = fmaxf(av.w, 0.f);
        }
        As[ac4 + 0][ar] = av.x;
        As[ac4 + 1][ar] = av.y;
        As[ac4 + 2][ar] = av.z;
        As[ac4 + 3][ar] = av.w;

        // B tile: [16 rows][64 cols]
        float4 bv = *(const float4*)(B + (size_t)(k0 + br) * DIM + col0 + bc4);
        *(float4*)&Bs[br][bc4] = bv;

        __syncthreads();

#pragma unroll
        for (int k = 0; k < BK; k++) {
            float a[4], b[4];
            *(float4*)a = *(const float4*)&As[k][ty * 4];
            *(float4*)b = *(const float4*)&Bs[k][tx * 4];
#pragma unroll
            for (int i = 0; i < 4; i++)
#pragma unroll
                for (int j = 0; j < 4; j++)
                    acc[i][j] = fmaf(a[i], b[j], acc[i][j]);
        }
        __syncthreads();
    }

    float4 bb = make_float4(0.f, 0.f, 0.f, 0.f);
    if (has_bias)
        bb = *(const float4*)(bias + col0 + tx * 4);

#pragma unroll
    for (int i = 0; i < 4; i++) {
        int r = row0 + ty * 4 + i;
        if (r < N_NODES) {
            float4 o;
            o.x = acc[i][0] + bb.x;
            o.y = acc[i][1] + bb.y;
            o.z = acc[i][2] + bb.z;
            o.w = acc[i][3] + bb.w;
            *(float4*)(C + (size_t)r * DIM + col0 + tx * 4) = o;
        }
    }
}

// ---------------- edge scatter: out[dst] += xr[r][src] * scale ----------------
// 96 threads (3 warps) per edge; each thread handles 4 consecutive floats.
// atomicAdd with unused result lowers to REDG (no-return reduction).
__global__ __launch_bounds__(256) void scatter_kernel(float* __restrict__ dout, int out_sel)
{
    float* out = (out_sel == 0) ? g_h1 : (out_sel == 1) ? g_h2 : dout;

    long long t = (long long)blockIdx.x * blockDim.x + threadIdx.x;
    if (t >= (long long)N_EDGES * 96) return;
    int e = (int)(t / 96);
    int c = (int)(t - (long long)e * 96) * 4;

    float s = g_scale[e];
    const float4 v = *(const float4*)(g_xr + g_srcoff[e] + c);
    float* p = out + g_dstoff[e] + c;
    atomicAdd(p + 0, v.x * s);
    atomicAdd(p + 1, v.y * s);
    atomicAdd(p + 2, v.z * s);
    atomicAdd(p + 3, v.w * s);
}

// ---------------- launch ----------------
extern "C" void kernel_launch(void* const* d_in, const int* in_sizes, int n_in,
                              void* d_out, int out_size)
{
    const float* emb = (const float*)d_in[0];
    const int*   ei  = (const int*)d_in[1];   // int64 in ref -> int32 in harness
    const int*   et  = (const int*)d_in[2];
    const float* W1 = (const float*)d_in[3];
    const float* r1 = (const float*)d_in[4];
    const float* b1 = (const float*)d_in[5];
    const float* W2 = (const float*)d_in[6];
    const float* r2 = (const float*)d_in[7];
    const float* b2 = (const float*)d_in[8];
    const float* W3 = (const float*)d_in[9];
    const float* r3 = (const float*)d_in[10];
    const float* b3 = (const float*)d_in[11];
    float* out = (float*)d_out;

    // edge preprocessing
    zero_cnt_kernel<<<(N_NODES * NREL + 255) / 256, 256>>>();
    count_kernel<<<(N_EDGES + 255) / 256, 256>>>(ei, et);
    build_edge_kernel<<<(N_EDGES + 255) / 256, 256>>>(ei, et);

    dim3 ggrid((N_NODES + BM - 1) / BM, DIM / BN, 3);
    long long sc_threads = (long long)N_EDGES * 96;
    int sc_blocks = (int)((sc_threads + 255) / 256);

    // layer 1: in = embeddings (no relu), accumulate into g_h1
    gemm3_kernel<<<ggrid, 256>>>(emb, 0, r1, W1, b1, out, 0, 0);
    scatter_kernel<<<sc_blocks, 256>>>(out, 0);

    // layer 2: in = relu(g_h1), accumulate into g_h2
    gemm3_kernel<<<ggrid, 256>>>(nullptr, 1, r2, W2, b2, out, 1, 1);
    scatter_kernel<<<sc_blocks, 256>>>(out, 1);

    // layer 3: in = relu(g_h2), accumulate into d_out
    gemm3_kernel<<<ggrid, 256>>>(nullptr, 2, r3, W3, b3, out, 2, 1);
    scatter_kernel<<<sc_blocks, 256>>>(out, 2);
}

// round 5
// speedup vs baseline: 1.4147x; 1.4147x over previous
#include <cuda_runtime.h>
#include <cuda_bf16.h>
#include <cstdint>

#define N_NODES 50000
#define M_PAD   50048            // 391 * 128
#define N_EDGES 200000
#define DIM     384
#define NREL    2

#define TM 128                   // M tile per CTA
#define TN 192                   // N tile per CTA
#define KC 128                   // K chunk
#define MTILES 391               // M_PAD / TM
#define RS 136                   // smem row stride in bf16 (128 + 8 pad -> conflict-free LDSM)

// smem byte offsets
#define SA_H 0
#define SA_L (TM * RS * 2)                    // 34816
#define SB_H (2 * TM * RS * 2)                // 69632
#define SB_L (SB_H + TN * RS * 2)             // 121856
#define SMEM_TOTAL (SB_L + TN * RS * 2)       // 174080

// ---------------- device scratch (no runtime allocation allowed) ----------------
__device__ __align__(16) float g_xr[(size_t)NREL * N_NODES * DIM];
__device__ __align__(16) float g_h1[(size_t)N_NODES * DIM];
__device__ __align__(16) float g_h2[(size_t)N_NODES * DIM];
__device__ __align__(16) __nv_bfloat16 g_ah[(size_t)M_PAD * DIM];    // A hi
__device__ __align__(16) __nv_bfloat16 g_al[(size_t)M_PAD * DIM];    // A lo
__device__ __align__(16) __nv_bfloat16 g_wth[(size_t)9 * DIM * DIM]; // W^T hi [mat][n][k]
__device__ __align__(16) __nv_bfloat16 g_wtl[(size_t)9 * DIM * DIM]; // W^T lo
__device__ int   g_cnt[N_NODES * NREL];
__device__ int   g_srcoff[N_EDGES];
__device__ int   g_dstoff[N_EDGES];
__device__ float g_scale[N_EDGES];

// ---------------- helpers ----------------
__device__ __forceinline__ uint32_t smem_u32(const void* p) {
    uint32_t a;
    asm("{ .reg .u64 t; cvta.to.shared.u64 t, %1; cvt.u32.u64 %0, t; }" : "=r"(a) : "l"(p));
    return a;
}
#define LDSM_X4(r, a)                                                                   \
    asm volatile("ldmatrix.sync.aligned.m8n8.x4.shared.b16 {%0,%1,%2,%3}, [%4];"        \
        : "=r"((r)[0]), "=r"((r)[1]), "=r"((r)[2]), "=r"((r)[3]) : "r"(a))

__device__ __forceinline__ void mma16816(float* d, const uint32_t* a,
                                         uint32_t b0, uint32_t b1) {
    asm volatile("mma.sync.aligned.m16n8k16.row.col.f32.bf16.bf16.f32 "
        "{%0,%1,%2,%3}, {%4,%5,%6,%7}, {%8,%9}, {%0,%1,%2,%3};"
        : "+f"(d[0]), "+f"(d[1]), "+f"(d[2]), "+f"(d[3])
        : "r"(a[0]), "r"(a[1]), "r"(a[2]), "r"(a[3]), "r"(b0), "r"(b1));
}

// ---------------- edge preprocessing ----------------
__global__ void zero_cnt_kernel() {
    int i = blockIdx.x * blockDim.x + threadIdx.x;
    if (i < N_NODES * NREL) g_cnt[i] = 0;
}
__device__ __forceinline__ int clampi(int v, int hi) {
    v = v < 0 ? 0 : v;
    return v >= hi ? hi - 1 : v;
}
__global__ void count_kernel(const int* __restrict__ ei, const int* __restrict__ et) {
    int e = blockIdx.x * blockDim.x + threadIdx.x;
    if (e >= N_EDGES) return;
    atomicAdd(&g_cnt[clampi(ei[N_EDGES + e], N_NODES) * NREL + clampi(et[e], NREL)], 1);
}
__global__ void build_edge_kernel(const int* __restrict__ ei, const int* __restrict__ et) {
    int e = blockIdx.x * blockDim.x + threadIdx.x;
    if (e >= N_EDGES) return;
    int src = clampi(ei[e], N_NODES);
    int dst = clampi(ei[N_EDGES + e], N_NODES);
    int r   = clampi(et[e], NREL);
    g_srcoff[e] = r * (N_NODES * DIM) + src * DIM;
    g_dstoff[e] = dst * DIM;
    int c = g_cnt[dst * NREL + r];
    g_scale[e] = 1.0f / (float)(c > 0 ? c : 1);
}

// ---------------- input split: x -> bf16 hi/lo (optional relu), zero-padded ----------------
__global__ void convert_x_kernel(const float* __restrict__ ext, int a_sel, int relu) {
    size_t i = (size_t)blockIdx.x * blockDim.x + threadIdx.x;
    if (i >= (size_t)M_PAD * DIM) return;
    const float* src = (a_sel == 0) ? ext : (a_sel == 1) ? g_h1 : g_h2;
    int row = (int)(i / DIM);
    float v = (row < N_NODES) ? src[i] : 0.0f;
    if (relu) v = fmaxf(v, 0.0f);
    __nv_bfloat16 h = __float2bfloat16(v);
    g_ah[i] = h;
    g_al[i] = __float2bfloat16(v - __bfloat162float(h));
}

// ---------------- weight transpose+split: W[k][n] -> WT[mat][n][k] hi/lo ----------------
__global__ void convert_w_kernel(const float* __restrict__ W1, const float* __restrict__ r1,
                                 const float* __restrict__ W2, const float* __restrict__ r2,
                                 const float* __restrict__ W3, const float* __restrict__ r3) {
    size_t i = (size_t)blockIdx.x * blockDim.x + threadIdx.x;
    if (i >= (size_t)9 * DIM * DIM) return;
    int m = (int)(i / (DIM * DIM));
    int rr = (int)(i % (DIM * DIM));
    int n = rr / DIM, k = rr % DIM;
    int L = m / 3, t = m % 3;
    const float* root = (L == 0) ? r1 : (L == 1) ? r2 : r3;
    const float* Wr   = (L == 0) ? W1 : (L == 1) ? W2 : W3;
    const float* src  = (t == 0) ? root : Wr + (size_t)(t - 1) * DIM * DIM;
    float v = src[(size_t)k * DIM + n];
    __nv_bfloat16 h = __float2bfloat16(v);
    g_wth[i] = h;
    g_wtl[i] = __float2bfloat16(v - __bfloat162float(h));
}

// ---------------- bf16x3 GEMM via mma.sync (family-portable tensor cores) ----------------
// grid (MTILES, 2, 3): z=0 -> root (bias, h/out), z=1/2 -> g_xr[z-1]
__global__ __launch_bounds__(256) void gemm_mma_kernel(
    int layer, const float* __restrict__ bias,
    float* __restrict__ dout, int out_sel)
{
    extern __shared__ char smem[];
    const uint32_t sbase = smem_u32(smem);
    const int tid = threadIdx.x;
    const int wid = tid >> 5, lane = tid & 31;
    const int z = blockIdx.z;
    const int row0 = blockIdx.x * TM;
    const int n0 = blockIdx.y * TN;
    const int mat = layer * 3 + z;

    float* C = (z == 0)
        ? ((out_sel == 0) ? g_h1 : (out_sel == 1) ? g_h2 : dout)
        : g_xr + (size_t)(z - 1) * N_NODES * DIM;

    const __nv_bfloat16* wth = g_wth + (size_t)mat * DIM * DIM;
    const __nv_bfloat16* wtl = g_wtl + (size_t)mat * DIM * DIM;

    const int wr = (wid & 3) * 32;   // warp row offset in tile
    const int wc = (wid >> 2) * 96;  // warp col offset in tile

    float acc[96];
#pragma unroll
    for (int i = 0; i < 96; i++) acc[i] = 0.0f;

    const int lrow = lane & 15;
    const int lcol8 = (lane >> 4) * 8;

    for (int kc = 0; kc < 3; kc++) {
        const int k0 = kc * KC;
        // ---- load A chunk hi+lo: 2 x [128][128] bf16 (uint4 = 8 bf16) ----
        for (int u = tid; u < 4096; u += 256) {
            int buf = u >> 11, rem = u & 2047;
            int row = rem >> 4, c8 = (rem & 15) * 8;
            const __nv_bfloat16* s = (buf ? g_al : g_ah)
                + (size_t)(row0 + row) * DIM + k0 + c8;
            *(uint4*)(smem + (buf ? SA_L : SA_H) + (row * RS + c8) * 2) = *(const uint4*)s;
        }
        // ---- load B chunk hi+lo: 2 x [192][128] bf16 ----
        for (int u = tid; u < 6144; u += 256) {
            int buf = (u >= 3072), rem = u - (buf ? 3072 : 0);
            int row = rem >> 4, c8 = (rem & 15) * 8;
            const __nv_bfloat16* s = (buf ? wtl : wth)
                + (size_t)(n0 + row) * DIM + k0 + c8;
            *(uint4*)(smem + (buf ? SB_L : SB_H) + (row * RS + c8) * 2) = *(const uint4*)s;
        }
        __syncthreads();

        // ---- 3 passes: (Ah,Bh), (Ah,Bl), (Al,Bh) ----
#pragma unroll 1
        for (int pass = 0; pass < 3; pass++) {
            const uint32_t abase = sbase + (pass == 2 ? SA_L : SA_H);
            const uint32_t bbase = sbase + (pass == 1 ? SB_L : SB_H);
#pragma unroll 1
            for (int ks = 0; ks < 8; ks++) {
                const int kk = ks * 16;
                uint32_t a[2][4];
#pragma unroll
                for (int mt = 0; mt < 2; mt++)
                    LDSM_X4(a[mt], abase + ((wr + mt * 16 + lrow) * RS + kk + lcol8) * 2);
#pragma unroll
                for (int g = 0; g < 6; g++) {
                    uint32_t b[4];
                    LDSM_X4(b, bbase + ((wc + g * 16 + lrow) * RS + kk + lcol8) * 2);
#pragma unroll
                    for (int mt = 0; mt < 2; mt++) {
                        mma16816(&acc[(mt * 12 + 2 * g) * 4], a[mt], b[0], b[2]);
                        mma16816(&acc[(mt * 12 + 2 * g + 1) * 4], a[mt], b[1], b[3]);
                    }
                }
            }
        }
        __syncthreads();
    }

    // ---- epilogue ----
    const int qr = lane >> 2, qc = (lane & 3) * 2;
#pragma unroll
    for (int mt = 0; mt < 2; mt++) {
#pragma unroll
        for (int nt = 0; nt < 12; nt++) {
            const float* d = &acc[(mt * 12 + nt) * 4];
            int m0 = row0 + wr + mt * 16 + qr;
            int n = n0 + wc + nt * 8 + qc;
            float bx = 0.f, by = 0.f;
            if (z == 0) {
                float2 bb = *(const float2*)(bias + n);
                bx = bb.x; by = bb.y;
            }
            if (m0 < N_NODES)
                *(float2*)(C + (size_t)m0 * DIM + n) = make_float2(d[0] + bx, d[1] + by);
            if (m0 + 8 < N_NODES)
                *(float2*)(C + (size_t)(m0 + 8) * DIM + n) = make_float2(d[2] + bx, d[3] + by);
        }
    }
}

// ---------------- edge scatter: out[dst] += xr[r][src] * scale ----------------
__global__ __launch_bounds__(256) void scatter_kernel(float* __restrict__ dout, int out_sel)
{
    float* out = (out_sel == 0) ? g_h1 : (out_sel == 1) ? g_h2 : dout;
    long long t = (long long)blockIdx.x * blockDim.x + threadIdx.x;
    if (t >= (long long)N_EDGES * 96) return;
    int e = (int)(t / 96);
    int c = (int)(t - (long long)e * 96) * 4;
    float s = g_scale[e];
    const float4 v = *(const float4*)(g_xr + g_srcoff[e] + c);
    float* p = out + g_dstoff[e] + c;
    atomicAdd(p + 0, v.x * s);
    atomicAdd(p + 1, v.y * s);
    atomicAdd(p + 2, v.z * s);
    atomicAdd(p + 3, v.w * s);
}

// ---------------- launch ----------------
extern "C" void kernel_launch(void* const* d_in, const int* in_sizes, int n_in,
                              void* d_out, int out_size)
{
    const float* emb = (const float*)d_in[0];
    const int*   ei  = (const int*)d_in[1];
    const int*   et  = (const int*)d_in[2];
    const float* W1 = (const float*)d_in[3];
    const float* r1 = (const float*)d_in[4];
    const float* b1 = (const float*)d_in[5];
    const float* W2 = (const float*)d_in[6];
    const float* r2 = (const float*)d_in[7];
    const float* b2 = (const float*)d_in[8];
    const float* W3 = (const float*)d_in[9];
    const float* r3 = (const float*)d_in[10];
    const float* b3 = (const float*)d_in[11];
    float* out = (float*)d_out;

    cudaFuncSetAttribute(gemm_mma_kernel,
                         cudaFuncAttributeMaxDynamicSharedMemorySize, SMEM_TOTAL);

    zero_cnt_kernel<<<(N_NODES * NREL + 255) / 256, 256>>>();
    count_kernel<<<(N_EDGES + 255) / 256, 256>>>(ei, et);
    build_edge_kernel<<<(N_EDGES + 255) / 256, 256>>>(ei, et);
    convert_w_kernel<<<(9 * DIM * DIM + 255) / 256, 256>>>(W1, r1, W2, r2, W3, r3);

    dim3 ggrid(MTILES, 2, 3);
    long long sc_threads = (long long)N_EDGES * 96;
    int sc_blocks = (int)((sc_threads + 255) / 256);
    int cv_blocks = (int)(((size_t)M_PAD * DIM + 511) / 512);

    // layer 1
    convert_x_kernel<<<cv_blocks, 512>>>(emb, 0, 0);
    gemm_mma_kernel<<<ggrid, 256, SMEM_TOTAL>>>(0, b1, out, 0);
    scatter_kernel<<<sc_blocks, 256>>>(out, 0);
    // layer 2
    convert_x_kernel<<<cv_blocks, 512>>>(nullptr, 1, 1);
    gemm_mma_kernel<<<ggrid, 256, SMEM_TOTAL>>>(1, b2, out, 1);
    scatter_kernel<<<sc_blocks, 256>>>(out, 1);
    // layer 3
    convert_x_kernel<<<cv_blocks, 512>>>(nullptr, 2, 1);
    gemm_mma_kernel<<<ggrid, 256, SMEM_TOTAL>>>(2, b3, out, 2);
    scatter_kernel<<<sc_blocks, 256>>>(out, 2);
}

// round 6
// speedup vs baseline: 1.8859x; 1.3331x over previous
#include <cuda_runtime.h>
#include <cuda_bf16.h>
#include <cstdint>

#define N_NODES 50000
#define M_PAD   50048            // 391 * 128
#define N_EDGES 200000
#define DIM     384
#define NREL    2

#define TM 128
#define TN 128
#define KC 32
#define NCHUNK 12               // DIM / KC
#define MTILES 391
#define PRB 80                  // padded row bytes (32 bf16 = 64B data + 16B pad)

// per-stage smem layout (bytes)
#define ST_AH 0
#define ST_AL (TM * PRB)                  // 10240
#define ST_BH (2 * TM * PRB)              // 20480
#define ST_BL (2 * TM * PRB + TN * PRB)   // 30720
#define STAGE_BYTES (2 * TM * PRB + 2 * TN * PRB)   // 40960
#define SMEM_TOTAL (2 * STAGE_BYTES)                // 81920

// ---------------- device scratch ----------------
__device__ __align__(16) float g_xr[(size_t)NREL * N_NODES * DIM];
__device__ __align__(16) float g_h1[(size_t)N_NODES * DIM];
__device__ __align__(16) float g_h2[(size_t)N_NODES * DIM];
__device__ __align__(16) __nv_bfloat16 g_ah[(size_t)M_PAD * DIM];
__device__ __align__(16) __nv_bfloat16 g_al[(size_t)M_PAD * DIM];
__device__ __align__(16) __nv_bfloat16 g_wth[(size_t)9 * DIM * DIM]; // [mat][n][k]
__device__ __align__(16) __nv_bfloat16 g_wtl[(size_t)9 * DIM * DIM];
__device__ int   g_cnt[N_NODES * NREL];
__device__ int   g_srcoff[N_EDGES];
__device__ int   g_dstoff[N_EDGES];
__device__ float g_scale[N_EDGES];

// ---------------- helpers ----------------
__device__ __forceinline__ uint32_t smem_u32(const void* p) {
    uint32_t a;
    asm("{ .reg .u64 t; cvta.to.shared.u64 t, %1; cvt.u32.u64 %0, t; }" : "=r"(a) : "l"(p));
    return a;
}
#define LDSM_X4(r, a)                                                                   \
    asm volatile("ldmatrix.sync.aligned.m8n8.x4.shared.b16 {%0,%1,%2,%3}, [%4];"        \
        : "=r"((r)[0]), "=r"((r)[1]), "=r"((r)[2]), "=r"((r)[3]) : "r"(a))
#define CP_ASYNC16(dst, src) \
    asm volatile("cp.async.cg.shared.global [%0], [%1], 16;" :: "r"(dst), "l"(src))
#define CP_COMMIT()  asm volatile("cp.async.commit_group;" ::: "memory")
#define CP_WAIT1()   asm volatile("cp.async.wait_group 1;" ::: "memory")
#define CP_WAIT0()   asm volatile("cp.async.wait_group 0;" ::: "memory")

__device__ __forceinline__ void mma16816(float* d, const uint32_t* a,
                                         uint32_t b0, uint32_t b1) {
    asm volatile("mma.sync.aligned.m16n8k16.row.col.f32.bf16.bf16.f32 "
        "{%0,%1,%2,%3}, {%4,%5,%6,%7}, {%8,%9}, {%0,%1,%2,%3};"
        : "+f"(d[0]), "+f"(d[1]), "+f"(d[2]), "+f"(d[3])
        : "r"(a[0]), "r"(a[1]), "r"(a[2]), "r"(a[3]), "r"(b0), "r"(b1));
}

// ---------------- edge preprocessing ----------------
__global__ void zero_cnt_kernel() {
    int i = blockIdx.x * blockDim.x + threadIdx.x;
    if (i < N_NODES * NREL) g_cnt[i] = 0;
}
__device__ __forceinline__ int clampi(int v, int hi) {
    v = v < 0 ? 0 : v;
    return v >= hi ? hi - 1 : v;
}
__global__ void count_kernel(const int* __restrict__ ei, const int* __restrict__ et) {
    int e = blockIdx.x * blockDim.x + threadIdx.x;
    if (e >= N_EDGES) return;
    atomicAdd(&g_cnt[clampi(ei[N_EDGES + e], N_NODES) * NREL + clampi(et[e], NREL)], 1);
}
__global__ void build_edge_kernel(const int* __restrict__ ei, const int* __restrict__ et) {
    int e = blockIdx.x * blockDim.x + threadIdx.x;
    if (e >= N_EDGES) return;
    int src = clampi(ei[e], N_NODES);
    int dst = clampi(ei[N_EDGES + e], N_NODES);
    int r   = clampi(et[e], NREL);
    g_srcoff[e] = r * (N_NODES * DIM) + src * DIM;
    g_dstoff[e] = dst * DIM;
    int c = g_cnt[dst * NREL + r];
    g_scale[e] = 1.0f / (float)(c > 0 ? c : 1);
}

// ---------------- input split ----------------
__global__ void convert_x_kernel(const float* __restrict__ ext, int a_sel, int relu) {
    size_t i = (size_t)blockIdx.x * blockDim.x + threadIdx.x;
    if (i >= (size_t)M_PAD * DIM) return;
    const float* src = (a_sel == 0) ? ext : (a_sel == 1) ? g_h1 : g_h2;
    int row = (int)(i / DIM);
    float v = (row < N_NODES) ? src[i] : 0.0f;
    if (relu) v = fmaxf(v, 0.0f);
    __nv_bfloat16 h = __float2bfloat16(v);
    g_ah[i] = h;
    g_al[i] = __float2bfloat16(v - __bfloat162float(h));
}

// ---------------- weight transpose+split ----------------
__global__ void convert_w_kernel(const float* __restrict__ W1, const float* __restrict__ r1,
                                 const float* __restrict__ W2, const float* __restrict__ r2,
                                 const float* __restrict__ W3, const float* __restrict__ r3) {
    size_t i = (size_t)blockIdx.x * blockDim.x + threadIdx.x;
    if (i >= (size_t)9 * DIM * DIM) return;
    int m = (int)(i / (DIM * DIM));
    int rr = (int)(i % (DIM * DIM));
    int n = rr / DIM, k = rr % DIM;
    int L = m / 3, t = m % 3;
    const float* root = (L == 0) ? r1 : (L == 1) ? r2 : r3;
    const float* Wr   = (L == 0) ? W1 : (L == 1) ? W2 : W3;
    const float* src  = (t == 0) ? root : Wr + (size_t)(t - 1) * DIM * DIM;
    float v = src[(size_t)k * DIM + n];
    __nv_bfloat16 h = __float2bfloat16(v);
    g_wth[i] = h;
    g_wtl[i] = __float2bfloat16(v - __bfloat162float(h));
}

// ---------------- pipelined bf16x3 GEMM via mma.sync ----------------
// grid (MTILES, 3, 3): y = n-tile (128 cols), z = mat (0 root -> C h/out + bias, 1/2 -> g_xr)
__device__ __forceinline__ void issue_chunk(
    uint32_t sb, const __nv_bfloat16* __restrict__ bh, const __nv_bfloat16* __restrict__ bl,
    int row0, int n0, int k0, int tid)
{
#pragma unroll
    for (int i = 0; i < 8; i++) {
        int u = tid + i * 256;
        int buf = u >> 9;            // 0: Ah, 1: Al, 2: Bh, 3: Bl
        int rem = u & 511;
        int row = rem >> 2;
        int c8  = (rem & 3) * 8;
        const __nv_bfloat16* src;
        if (buf == 0)      src = g_ah + (size_t)(row0 + row) * DIM + k0 + c8;
        else if (buf == 1) src = g_al + (size_t)(row0 + row) * DIM + k0 + c8;
        else if (buf == 2) src = bh + (size_t)(n0 + row) * DIM + k0 + c8;
        else               src = bl + (size_t)(n0 + row) * DIM + k0 + c8;
        uint32_t dst = sb + buf * 10240 + row * PRB + c8 * 2;
        CP_ASYNC16(dst, src);
    }
    CP_COMMIT();
}

__global__ __launch_bounds__(256, 2) void gemm_mma_kernel(
    int layer, const float* __restrict__ bias,
    float* __restrict__ dout, int out_sel)
{
    extern __shared__ char smem[];
    const uint32_t sbase = smem_u32(smem);
    const int tid = threadIdx.x;
    const int wid = tid >> 5, lane = tid & 31;
    const int z = blockIdx.z;
    const int row0 = blockIdx.x * TM;
    const int n0 = blockIdx.y * TN;
    const int mat = layer * 3 + z;

    float* C = (z == 0)
        ? ((out_sel == 0) ? g_h1 : (out_sel == 1) ? g_h2 : dout)
        : g_xr + (size_t)(z - 1) * N_NODES * DIM;

    const __nv_bfloat16* wth = g_wth + (size_t)mat * DIM * DIM;
    const __nv_bfloat16* wtl = g_wtl + (size_t)mat * DIM * DIM;

    const int wr = (wid >> 1) * 32;   // warp row offset (4 row-warps)
    const int wc = (wid & 1) * 64;    // warp col offset (2 col-warps)
    const int lrow = lane & 15;
    const int lcol8 = (lane >> 4) * 8;

    float acc[64];
#pragma unroll
    for (int i = 0; i < 64; i++) acc[i] = 0.0f;

    issue_chunk(sbase, wth, wtl, row0, n0, 0, tid);

    for (int c = 0; c < NCHUNK; c++) {
        if (c + 1 < NCHUNK) {
            issue_chunk(sbase + ((c + 1) & 1) * STAGE_BYTES, wth, wtl,
                        row0, n0, (c + 1) * KC, tid);
            CP_WAIT1();
        } else {
            CP_WAIT0();
        }
        __syncthreads();

        const uint32_t stg = sbase + (c & 1) * STAGE_BYTES;
#pragma unroll
        for (int pass = 0; pass < 3; pass++) {
            const uint32_t ab = stg + (pass == 2 ? ST_AL : ST_AH);
            const uint32_t bb = stg + (pass == 1 ? ST_BL : ST_BH);
#pragma unroll
            for (int ks = 0; ks < 2; ks++) {
                const int kk = ks * 16;
                uint32_t a[2][4], b[4][4];
#pragma unroll
                for (int mt = 0; mt < 2; mt++)
                    LDSM_X4(a[mt], ab + (wr + mt * 16 + lrow) * PRB + (kk + lcol8) * 2);
#pragma unroll
                for (int g = 0; g < 4; g++)
                    LDSM_X4(b[g], bb + (wc + g * 16 + lrow) * PRB + (kk + lcol8) * 2);
#pragma unroll
                for (int mt = 0; mt < 2; mt++)
#pragma unroll
                    for (int g = 0; g < 4; g++) {
                        mma16816(&acc[((mt * 4 + g) * 2 + 0) * 4], a[mt], b[g][0], b[g][2]);
                        mma16816(&acc[((mt * 4 + g) * 2 + 1) * 4], a[mt], b[g][1], b[g][3]);
                    }
            }
        }
        __syncthreads();
    }

    // ---- epilogue ----
    const int qr = lane >> 2, qc = (lane & 3) * 2;
#pragma unroll
    for (int mt = 0; mt < 2; mt++) {
#pragma unroll
        for (int nt = 0; nt < 8; nt++) {
            const float* d = &acc[((mt * 4 + (nt >> 1)) * 2 + (nt & 1)) * 4];
            int m0 = row0 + wr + mt * 16 + qr;
            int n = n0 + wc + (nt >> 1) * 16 + (nt & 1) * 8 + qc;
            float bx = 0.f, by = 0.f;
            if (z == 0) {
                float2 bb = *(const float2*)(bias + n);
                bx = bb.x; by = bb.y;
            }
            if (m0 < N_NODES)
                *(float2*)(C + (size_t)m0 * DIM + n) = make_float2(d[0] + bx, d[1] + by);
            if (m0 + 8 < N_NODES)
                *(float2*)(C + (size_t)(m0 + 8) * DIM + n) = make_float2(d[2] + bx, d[3] + by);
        }
    }
}

// ---------------- edge scatter ----------------
__global__ __launch_bounds__(256) void scatter_kernel(float* __restrict__ dout, int out_sel)
{
    float* out = (out_sel == 0) ? g_h1 : (out_sel == 1) ? g_h2 : dout;
    long long t = (long long)blockIdx.x * blockDim.x + threadIdx.x;
    if (t >= (long long)N_EDGES * 96) return;
    int e = (int)(t / 96);
    int c = (int)(t - (long long)e * 96) * 4;
    float s = g_scale[e];
    const float4 v = *(const float4*)(g_xr + g_srcoff[e] + c);
    float* p = out + g_dstoff[e] + c;
    atomicAdd(p + 0, v.x * s);
    atomicAdd(p + 1, v.y * s);
    atomicAdd(p + 2, v.z * s);
    atomicAdd(p + 3, v.w * s);
}

// ---------------- launch ----------------
extern "C" void kernel_launch(void* const* d_in, const int* in_sizes, int n_in,
                              void* d_out, int out_size)
{
    const float* emb = (const float*)d_in[0];
    const int*   ei  = (const int*)d_in[1];
    const int*   et  = (const int*)d_in[2];
    const float* W1 = (const float*)d_in[3];
    const float* r1 = (const float*)d_in[4];
    const float* b1 = (const float*)d_in[5];
    const float* W2 = (const float*)d_in[6];
    const float* r2 = (const float*)d_in[7];
    const float* b2 = (const float*)d_in[8];
    const float* W3 = (const float*)d_in[9];
    const float* r3 = (const float*)d_in[10];
    const float* b3 = (const float*)d_in[11];
    float* out = (float*)d_out;

    cudaFuncSetAttribute(gemm_mma_kernel,
                         cudaFuncAttributeMaxDynamicSharedMemorySize, SMEM_TOTAL);

    zero_cnt_kernel<<<(N_NODES * NREL + 255) / 256, 256>>>();
    count_kernel<<<(N_EDGES + 255) / 256, 256>>>(ei, et);
    build_edge_kernel<<<(N_EDGES + 255) / 256, 256>>>(ei, et);
    convert_w_kernel<<<(9 * DIM * DIM + 255) / 256, 256>>>(W1, r1, W2, r2, W3, r3);

    dim3 ggrid(MTILES, 3, 3);
    long long sc_threads = (long long)N_EDGES * 96;
    int sc_blocks = (int)((sc_threads + 255) / 256);
    int cv_blocks = (int)(((size_t)M_PAD * DIM + 511) / 512);

    // layer 1
    convert_x_kernel<<<cv_blocks, 512>>>(emb, 0, 0);
    gemm_mma_kernel<<<ggrid, 256, SMEM_TOTAL>>>(0, b1, out, 0);
    scatter_kernel<<<sc_blocks, 256>>>(out, 0);
    // layer 2
    convert_x_kernel<<<cv_blocks, 512>>>(nullptr, 1, 1);
    gemm_mma_kernel<<<ggrid, 256, SMEM_TOTAL>>>(1, b2, out, 1);
    scatter_kernel<<<sc_blocks, 256>>>(out, 1);
    // layer 3
    convert_x_kernel<<<cv_blocks, 512>>>(nullptr, 2, 1);
    gemm_mma_kernel<<<ggrid, 256, SMEM_TOTAL>>>(2, b3, out, 2);
    scatter_kernel<<<sc_blocks, 256>>>(out, 2);
}

// round 7
// speedup vs baseline: 1.9502x; 1.0341x over previous
#include <cuda_runtime.h>
#include <cuda_bf16.h>
#include <cstdint>

#define N_NODES 50000
#define M_PAD   50048            // 391 * 128
#define N_EDGES 200000
#define DIM     384
#define NREL    2

#define TM 128
#define TN 128
#define KC 32
#define NCHUNK 12               // DIM / KC
#define MTILES 391
#define PRB 80                  // padded row bytes (32 bf16 = 64B data + 16B pad)

// per-stage smem layout (bytes)
#define ST_AH 0
#define ST_AL (TM * PRB)                  // 10240
#define ST_BH (2 * TM * PRB)              // 20480
#define ST_BL (2 * TM * PRB + TN * PRB)   // 30720
#define STAGE_BYTES (2 * TM * PRB + 2 * TN * PRB)   // 40960
#define SMEM_TOTAL (2 * STAGE_BYTES)                // 81920

// ---------------- device scratch ----------------
__device__ __align__(16) float g_xr[(size_t)NREL * N_NODES * DIM];
__device__ __align__(16) float g_h1[(size_t)N_NODES * DIM];
__device__ __align__(16) float g_h2[(size_t)N_NODES * DIM];
__device__ __align__(16) __nv_bfloat16 g_ah[(size_t)M_PAD * DIM];
__device__ __align__(16) __nv_bfloat16 g_al[(size_t)M_PAD * DIM];
__device__ __align__(16) __nv_bfloat16 g_wth[(size_t)9 * DIM * DIM]; // [mat][n][k]
__device__ __align__(16) __nv_bfloat16 g_wtl[(size_t)9 * DIM * DIM];
__device__ int   g_cnt[N_NODES * NREL];
__device__ int   g_srcoff[N_EDGES];
__device__ int   g_dstoff[N_EDGES];
__device__ float g_scale[N_EDGES];

// ---------------- helpers ----------------
__device__ __forceinline__ uint32_t smem_u32(const void* p) {
    uint32_t a;
    asm("{ .reg .u64 t; cvta.to.shared.u64 t, %1; cvt.u32.u64 %0, t; }" : "=r"(a) : "l"(p));
    return a;
}
#define LDSM_X4(r, a)                                                                   \
    asm volatile("ldmatrix.sync.aligned.m8n8.x4.shared.b16 {%0,%1,%2,%3}, [%4];"        \
        : "=r"((r)[0]), "=r"((r)[1]), "=r"((r)[2]), "=r"((r)[3]) : "r"(a))
#define CP_ASYNC16(dst, src) \
    asm volatile("cp.async.cg.shared.global [%0], [%1], 16;" :: "r"(dst), "l"(src))
#define CP_COMMIT()  asm volatile("cp.async.commit_group;" ::: "memory")
#define CP_WAIT1()   asm volatile("cp.async.wait_group 1;" ::: "memory")
#define CP_WAIT0()   asm volatile("cp.async.wait_group 0;" ::: "memory")

__device__ __forceinline__ void mma16816(float* d, const uint32_t* a,
                                         uint32_t b0, uint32_t b1) {
    asm volatile("mma.sync.aligned.m16n8k16.row.col.f32.bf16.bf16.f32 "
        "{%0,%1,%2,%3}, {%4,%5,%6,%7}, {%8,%9}, {%0,%1,%2,%3};"
        : "+f"(d[0]), "+f"(d[1]), "+f"(d[2]), "+f"(d[3])
        : "r"(a[0]), "r"(a[1]), "r"(a[2]), "r"(a[3]), "r"(b0), "r"(b1));
}

// ---------------- edge preprocessing ----------------
__global__ void zero_cnt_kernel() {
    int i = blockIdx.x * blockDim.x + threadIdx.x;
    if (i < N_NODES * NREL) g_cnt[i] = 0;
}
__device__ __forceinline__ int clampi(int v, int hi) {
    v = v < 0 ? 0 : v;
    return v >= hi ? hi - 1 : v;
}
__global__ void count_kernel(const int* __restrict__ ei, const int* __restrict__ et) {
    int e = blockIdx.x * blockDim.x + threadIdx.x;
    if (e >= N_EDGES) return;
    atomicAdd(&g_cnt[clampi(ei[N_EDGES + e], N_NODES) * NREL + clampi(et[e], NREL)], 1);
}
__global__ void build_edge_kernel(const int* __restrict__ ei, const int* __restrict__ et) {
    int e = blockIdx.x * blockDim.x + threadIdx.x;
    if (e >= N_EDGES) return;
    int src = clampi(ei[e], N_NODES);
    int dst = clampi(ei[N_EDGES + e], N_NODES);
    int r   = clampi(et[e], NREL);
    g_srcoff[e] = r * (N_NODES * DIM) + src * DIM;
    g_dstoff[e] = dst * DIM;
    int c = g_cnt[dst * NREL + r];
    g_scale[e] = 1.0f / (float)(c > 0 ? c : 1);
}

// ---------------- input split ----------------
__global__ void convert_x_kernel(const float* __restrict__ ext, int a_sel, int relu) {
    size_t i = (size_t)blockIdx.x * blockDim.x + threadIdx.x;
    if (i >= (size_t)M_PAD * DIM) return;
    const float* src = (a_sel == 0) ? ext : (a_sel == 1) ? g_h1 : g_h2;
    int row = (int)(i / DIM);
    float v = (row < N_NODES) ? src[i] : 0.0f;
    if (relu) v = fmaxf(v, 0.0f);
    __nv_bfloat16 h = __float2bfloat16(v);
    g_ah[i] = h;
    g_al[i] = __float2bfloat16(v - __bfloat162float(h));
}

// ---------------- weight transpose+split ----------------
__global__ void convert_w_kernel(const float* __restrict__ W1, const float* __restrict__ r1,
                                 const float* __restrict__ W2, const float* __restrict__ r2,
                                 const float* __restrict__ W3, const float* __restrict__ r3) {
    size_t i = (size_t)blockIdx.x * blockDim.x + threadIdx.x;
    if (i >= (size_t)9 * DIM * DIM) return;
    int m = (int)(i / (DIM * DIM));
    int rr = (int)(i % (DIM * DIM));
    int n = rr / DIM, k = rr % DIM;
    int L = m / 3, t = m % 3;
    const float* root = (L == 0) ? r1 : (L == 1) ? r2 : r3;
    const float* Wr   = (L == 0) ? W1 : (L == 1) ? W2 : W3;
    const float* src  = (t == 0) ? root : Wr + (size_t)(t - 1) * DIM * DIM;
    float v = src[(size_t)k * DIM + n];
    __nv_bfloat16 h = __float2bfloat16(v);
    g_wth[i] = h;
    g_wtl[i] = __float2bfloat16(v - __bfloat162float(h));
}

// ---------------- pipelined bf16x3 GEMM, fragment reuse across passes ----------------
// grid (MTILES, 3, 3): y = n-tile (128 cols), z = mat (0 root -> C h/out + bias, 1/2 -> g_xr)
__device__ __forceinline__ void issue_chunk(
    uint32_t sb, const __nv_bfloat16* __restrict__ bh, const __nv_bfloat16* __restrict__ bl,
    int row0, int n0, int k0, int tid)
{
#pragma unroll
    for (int i = 0; i < 8; i++) {
        int u = tid + i * 256;
        int buf = u >> 9;            // 0: Ah, 1: Al, 2: Bh, 3: Bl
        int rem = u & 511;
        int row = rem >> 2;
        int c8  = (rem & 3) * 8;
        const __nv_bfloat16* src;
        if (buf == 0)      src = g_ah + (size_t)(row0 + row) * DIM + k0 + c8;
        else if (buf == 1) src = g_al + (size_t)(row0 + row) * DIM + k0 + c8;
        else if (buf == 2) src = bh + (size_t)(n0 + row) * DIM + k0 + c8;
        else               src = bl + (size_t)(n0 + row) * DIM + k0 + c8;
        uint32_t dst = sb + buf * 10240 + row * PRB + c8 * 2;
        CP_ASYNC16(dst, src);
    }
    CP_COMMIT();
}

__global__ __launch_bounds__(256, 2) void gemm_mma_kernel(
    int layer, const float* __restrict__ bias,
    float* __restrict__ dout, int out_sel)
{
    extern __shared__ char smem[];
    const uint32_t sbase = smem_u32(smem);
    const int tid = threadIdx.x;
    const int wid = tid >> 5, lane = tid & 31;
    const int z = blockIdx.z;
    const int row0 = blockIdx.x * TM;
    const int n0 = blockIdx.y * TN;
    const int mat = layer * 3 + z;

    float* C = (z == 0)
        ? ((out_sel == 0) ? g_h1 : (out_sel == 1) ? g_h2 : dout)
        : g_xr + (size_t)(z - 1) * N_NODES * DIM;

    const __nv_bfloat16* wth = g_wth + (size_t)mat * DIM * DIM;
    const __nv_bfloat16* wtl = g_wtl + (size_t)mat * DIM * DIM;

    const int wr = (wid >> 1) * 32;   // warp row offset (4 row-warps)
    const int wc = (wid & 1) * 64;    // warp col offset (2 col-warps)
    const int lrow = lane & 15;
    const int lcol8 = (lane >> 4) * 8;

    float acc[64];
#pragma unroll
    for (int i = 0; i < 64; i++) acc[i] = 0.0f;

    issue_chunk(sbase, wth, wtl, row0, n0, 0, tid);

    for (int c = 0; c < NCHUNK; c++) {
        if (c + 1 < NCHUNK) {
            issue_chunk(sbase + ((c + 1) & 1) * STAGE_BYTES, wth, wtl,
                        row0, n0, (c + 1) * KC, tid);
            CP_WAIT1();
        } else {
            CP_WAIT0();
        }
        __syncthreads();

        const uint32_t stg = sbase + (c & 1) * STAGE_BYTES;
#pragma unroll
        for (int ks = 0; ks < 2; ks++) {
            const int kb = (ks * 16 + lcol8) * 2;
            // load all fragments for this 16-k step once
            uint32_t ah[2][4], al[2][4], bh[4][4], bl[4][4];
#pragma unroll
            for (int mt = 0; mt < 2; mt++) {
                const uint32_t ra = (wr + mt * 16 + lrow) * PRB + kb;
                LDSM_X4(ah[mt], stg + ST_AH + ra);
                LDSM_X4(al[mt], stg + ST_AL + ra);
            }
#pragma unroll
            for (int g = 0; g < 4; g++) {
                const uint32_t rb = (wc + g * 16 + lrow) * PRB + kb;
                LDSM_X4(bh[g], stg + ST_BH + rb);
                LDSM_X4(bl[g], stg + ST_BL + rb);
            }
            // 3 passes against cached fragments: Ah*Bh, Ah*Bl, Al*Bh
#pragma unroll
            for (int mt = 0; mt < 2; mt++)
#pragma unroll
                for (int g = 0; g < 4; g++) {
                    float* d0 = &acc[((mt * 4 + g) * 2 + 0) * 4];
                    float* d1 = &acc[((mt * 4 + g) * 2 + 1) * 4];
                    mma16816(d0, ah[mt], bh[g][0], bh[g][2]);
                    mma16816(d1, ah[mt], bh[g][1], bh[g][3]);
                    mma16816(d0, ah[mt], bl[g][0], bl[g][2]);
                    mma16816(d1, ah[mt], bl[g][1], bl[g][3]);
                    mma16816(d0, al[mt], bh[g][0], bh[g][2]);
                    mma16816(d1, al[mt], bh[g][1], bh[g][3]);
                }
        }
        __syncthreads();
    }

    // ---- epilogue ----
    const int qr = lane >> 2, qc = (lane & 3) * 2;
#pragma unroll
    for (int mt = 0; mt < 2; mt++) {
#pragma unroll
        for (int nt = 0; nt < 8; nt++) {
            const float* d = &acc[((mt * 4 + (nt >> 1)) * 2 + (nt & 1)) * 4];
            int m0 = row0 + wr + mt * 16 + qr;
            int n = n0 + wc + (nt >> 1) * 16 + (nt & 1) * 8 + qc;
            float bx = 0.f, by = 0.f;
            if (z == 0) {
                float2 bb = *(const float2*)(bias + n);
                bx = bb.x; by = bb.y;
            }
            if (m0 < N_NODES)
                *(float2*)(C + (size_t)m0 * DIM + n) = make_float2(d[0] + bx, d[1] + by);
            if (m0 + 8 < N_NODES)
                *(float2*)(C + (size_t)(m0 + 8) * DIM + n) = make_float2(d[2] + bx, d[3] + by);
        }
    }
}

// ---------------- edge scatter ----------------
__global__ __launch_bounds__(256) void scatter_kernel(float* __restrict__ dout, int out_sel)
{
    float* out = (out_sel == 0) ? g_h1 : (out_sel == 1) ? g_h2 : dout;
    long long t = (long long)blockIdx.x * blockDim.x + threadIdx.x;
    if (t >= (long long)N_EDGES * 96) return;
    int e = (int)(t / 96);
    int c = (int)(t - (long long)e * 96) * 4;
    float s = g_scale[e];
    const float4 v = *(const float4*)(g_xr + g_srcoff[e] + c);
    float* p = out + g_dstoff[e] + c;
    atomicAdd(p + 0, v.x * s);
    atomicAdd(p + 1, v.y * s);
    atomicAdd(p + 2, v.z * s);
    atomicAdd(p + 3, v.w * s);
}

// ---------------- launch ----------------
extern "C" void kernel_launch(void* const* d_in, const int* in_sizes, int n_in,
                              void* d_out, int out_size)
{
    const float* emb = (const float*)d_in[0];
    const int*   ei  = (const int*)d_in[1];
    const int*   et  = (const int*)d_in[2];
    const float* W1 = (const float*)d_in[3];
    const float* r1 = (const float*)d_in[4];
    const float* b1 = (const float*)d_in[5];
    const float* W2 = (const float*)d_in[6];
    const float* r2 = (const float*)d_in[7];
    const float* b2 = (const float*)d_in[8];
    const float* W3 = (const float*)d_in[9];
    const float* r3 = (const float*)d_in[10];
    const float* b3 = (const float*)d_in[11];
    float* out = (float*)d_out;

    cudaFuncSetAttribute(gemm_mma_kernel,
                         cudaFuncAttributeMaxDynamicSharedMemorySize, SMEM_TOTAL);

    zero_cnt_kernel<<<(N_NODES * NREL + 255) / 256, 256>>>();
    count_kernel<<<(N_EDGES + 255) / 256, 256>>>(ei, et);
    build_edge_kernel<<<(N_EDGES + 255) / 256, 256>>>(ei, et);
    convert_w_kernel<<<(9 * DIM * DIM + 255) / 256, 256>>>(W1, r1, W2, r2, W3, r3);

    dim3 ggrid(MTILES, 3, 3);
    long long sc_threads = (long long)N_EDGES * 96;
    int sc_blocks = (int)((sc_threads + 255) / 256);
    int cv_blocks = (int)(((size_t)M_PAD * DIM + 511) / 512);

    // layer 1
    convert_x_kernel<<<cv_blocks, 512>>>(emb, 0, 0);
    gemm_mma_kernel<<<ggrid, 256, SMEM_TOTAL>>>(0, b1, out, 0);
    scatter_kernel<<<sc_blocks, 256>>>(out, 0);
    // layer 2
    convert_x_kernel<<<cv_blocks, 512>>>(nullptr, 1, 1);
    gemm_mma_kernel<<<ggrid, 256, SMEM_TOTAL>>>(1, b2, out, 1);
    scatter_kernel<<<sc_blocks, 256>>>(out, 1);
    // layer 3
    convert_x_kernel<<<cv_blocks, 512>>>(nullptr, 2, 1);
    gemm_mma_kernel<<<ggrid, 256, SMEM_TOTAL>>>(2, b3, out, 2);
    scatter_kernel<<<sc_blocks, 256>>>(out, 2);
}

// round 8
// speedup vs baseline: 2.4998x; 1.2818x over previous
#include <cuda_runtime.h>
#include <cuda_bf16.h>
#include <cstdint>

#define N_NODES 50000
#define M_PAD   50048            // 391 * 128
#define N_EDGES 200000
#define DIM     384
#define NREL    2

#define TM 128
#define TN 128
#define KC 32
#define NCHUNK 12               // DIM / KC
#define MTILES 391
#define PRB 80                  // padded row bytes (32 bf16 = 64B data + 16B pad)

// per-stage smem layout (bytes)
#define ST_AH 0
#define ST_AL (TM * PRB)                  // 10240
#define ST_BH (2 * TM * PRB)              // 20480
#define ST_BL (2 * TM * PRB + TN * PRB)   // 30720
#define STAGE_BYTES (2 * TM * PRB + 2 * TN * PRB)   // 40960
#define SMEM_TOTAL (2 * STAGE_BYTES)                // 81920

// ---------------- device scratch ----------------
__device__ __align__(16) float g_xr[(size_t)NREL * N_NODES * DIM];
__device__ __align__(16) float g_h1[(size_t)N_NODES * DIM];
__device__ __align__(16) float g_h2[(size_t)N_NODES * DIM];
__device__ __align__(16) __nv_bfloat16 g_ah[(size_t)M_PAD * DIM];
__device__ __align__(16) __nv_bfloat16 g_al[(size_t)M_PAD * DIM];
__device__ __align__(16) __nv_bfloat16 g_wth[(size_t)9 * DIM * DIM]; // [mat][n][k]
__device__ __align__(16) __nv_bfloat16 g_wtl[(size_t)9 * DIM * DIM];
__device__ int   g_cnt[N_NODES * NREL];   // per (dst, rel) in-degree
__device__ int   g_cur[N_NODES];          // permute cursors
__device__ int   g_off[N_NODES + 1];      // CSR offsets by dst
__device__ int   g_psrc[N_EDGES];         // permuted: r*N*D + src*D
__device__ float g_pscale[N_EDGES];       // permuted: 1/max(cnt,1)

// ---------------- helpers ----------------
__device__ __forceinline__ uint32_t smem_u32(const void* p) {
    uint32_t a;
    asm("{ .reg .u64 t; cvta.to.shared.u64 t, %1; cvt.u32.u64 %0, t; }" : "=r"(a) : "l"(p));
    return a;
}
#define LDSM_X4(r, a)                                                                   \
    asm volatile("ldmatrix.sync.aligned.m8n8.x4.shared.b16 {%0,%1,%2,%3}, [%4];"        \
        : "=r"((r)[0]), "=r"((r)[1]), "=r"((r)[2]), "=r"((r)[3]) : "r"(a))
#define CP_ASYNC16(dst, src) \
    asm volatile("cp.async.cg.shared.global [%0], [%1], 16;" :: "r"(dst), "l"(src))
#define CP_COMMIT()  asm volatile("cp.async.commit_group;" ::: "memory")
#define CP_WAIT1()   asm volatile("cp.async.wait_group 1;" ::: "memory")
#define CP_WAIT0()   asm volatile("cp.async.wait_group 0;" ::: "memory")

__device__ __forceinline__ void mma16816(float* d, const uint32_t* a,
                                         uint32_t b0, uint32_t b1) {
    asm volatile("mma.sync.aligned.m16n8k16.row.col.f32.bf16.bf16.f32 "
        "{%0,%1,%2,%3}, {%4,%5,%6,%7}, {%8,%9}, {%0,%1,%2,%3};"
        : "+f"(d[0]), "+f"(d[1]), "+f"(d[2]), "+f"(d[3])
        : "r"(a[0]), "r"(a[1]), "r"(a[2]), "r"(a[3]), "r"(b0), "r"(b1));
}

// ---------------- edge preprocessing ----------------
__global__ void zero_kernel() {
    int i = blockIdx.x * blockDim.x + threadIdx.x;
    if (i < N_NODES * NREL) g_cnt[i] = 0;
    if (i < N_NODES) g_cur[i] = 0;
}
__device__ __forceinline__ int clampi(int v, int hi) {
    v = v < 0 ? 0 : v;
    return v >= hi ? hi - 1 : v;
}
__global__ void count_kernel(const int* __restrict__ ei, const int* __restrict__ et) {
    int e = blockIdx.x * blockDim.x + threadIdx.x;
    if (e >= N_EDGES) return;
    atomicAdd(&g_cnt[clampi(ei[N_EDGES + e], N_NODES) * NREL + clampi(et[e], NREL)], 1);
}

// single-block exclusive scan of per-dst total degree -> g_off
__global__ void scan_kernel() {
    __shared__ int wsum[32];
    __shared__ int carry;
    const int tid = threadIdx.x;
    const int lane = tid & 31, w = tid >> 5;
    if (tid == 0) carry = 0;
    __syncthreads();
    for (int base = 0; base < N_NODES; base += 1024) {
        int i = base + tid;
        int v = (i < N_NODES) ? (g_cnt[i * NREL] + g_cnt[i * NREL + 1]) : 0;
        int incl = v;
#pragma unroll
        for (int o = 1; o < 32; o <<= 1) {
            int n = __shfl_up_sync(0xFFFFFFFF, incl, o);
            if (lane >= o) incl += n;
        }
        if (lane == 31) wsum[w] = incl;
        __syncthreads();
        if (w == 0) {
            int s = (lane < 32) ? wsum[lane] : 0;
#pragma unroll
            for (int o = 1; o < 32; o <<= 1) {
                int n = __shfl_up_sync(0xFFFFFFFF, s, o);
                if (lane >= o) s += n;
            }
            wsum[lane] = s;
        }
        __syncthreads();
        int excl = incl - v + (w > 0 ? wsum[w - 1] : 0) + carry;
        if (i < N_NODES) g_off[i] = excl;
        __syncthreads();
        if (tid == 1023) carry += wsum[31] - wsum[30] + incl - (incl - v) - v + wsum[31];
        // (recompute carefully below instead)
        __syncthreads();
    }
}

// simpler & correct scan (replaces the above if used) -- see scan2_kernel
__global__ void scan2_kernel() {
    __shared__ int wsum[32];
    __shared__ int s_carry;
    const int tid = threadIdx.x;
    const int lane = tid & 31, w = tid >> 5;
    if (tid == 0) s_carry = 0;
    __syncthreads();
    for (int base = 0; base < N_NODES; base += 1024) {
        int i = base + tid;
        int v = (i < N_NODES) ? (g_cnt[i * NREL] + g_cnt[i * NREL + 1]) : 0;
        int incl = v;
#pragma unroll
        for (int o = 1; o < 32; o <<= 1) {
            int n = __shfl_up_sync(0xFFFFFFFF, incl, o);
            if (lane >= o) incl += n;
        }
        if (lane == 31) wsum[w] = incl;
        __syncthreads();
        if (w == 0) {
            int s = wsum[lane];
#pragma unroll
            for (int o = 1; o < 32; o <<= 1) {
                int n = __shfl_up_sync(0xFFFFFFFF, s, o);
                if (lane >= o) s += n;
            }
            wsum[lane] = s;
        }
        __syncthreads();
        int blk_excl = incl - v + (w > 0 ? wsum[w - 1] : 0);
        if (i < N_NODES) g_off[i] = s_carry + blk_excl;
        __syncthreads();
        if (tid == 0) s_carry += wsum[31];
        __syncthreads();
    }
    if (tid == 0) g_off[N_NODES] = s_carry;
}

__global__ void permute_kernel(const int* __restrict__ ei, const int* __restrict__ et) {
    int e = blockIdx.x * blockDim.x + threadIdx.x;
    if (e >= N_EDGES) return;
    int src = clampi(ei[e], N_NODES);
    int dst = clampi(ei[N_EDGES + e], N_NODES);
    int r   = clampi(et[e], NREL);
    int slot = g_off[dst] + atomicAdd(&g_cur[dst], 1);
    g_psrc[slot] = r * (N_NODES * DIM) + src * DIM;
    int c = g_cnt[dst * NREL + r];
    g_pscale[slot] = 1.0f / (float)(c > 0 ? c : 1);
}

// ---------------- input split (layer 1 only) ----------------
__global__ void convert_x_kernel(const float* __restrict__ ext) {
    size_t i = (size_t)blockIdx.x * blockDim.x + threadIdx.x;
    if (i >= (size_t)N_NODES * DIM) return;
    float v = ext[i];
    __nv_bfloat16 h = __float2bfloat16(v);
    g_ah[i] = h;
    g_al[i] = __float2bfloat16(v - __bfloat162float(h));
}

// ---------------- weight transpose+split ----------------
__global__ void convert_w_kernel(const float* __restrict__ W1, const float* __restrict__ r1,
                                 const float* __restrict__ W2, const float* __restrict__ r2,
                                 const float* __restrict__ W3, const float* __restrict__ r3) {
    size_t i = (size_t)blockIdx.x * blockDim.x + threadIdx.x;
    if (i >= (size_t)9 * DIM * DIM) return;
    int m = (int)(i / (DIM * DIM));
    int rr = (int)(i % (DIM * DIM));
    int n = rr / DIM, k = rr % DIM;
    int L = m / 3, t = m % 3;
    const float* root = (L == 0) ? r1 : (L == 1) ? r2 : r3;
    const float* Wr   = (L == 0) ? W1 : (L == 1) ? W2 : W3;
    const float* src  = (t == 0) ? root : Wr + (size_t)(t - 1) * DIM * DIM;
    float v = src[(size_t)k * DIM + n];
    __nv_bfloat16 h = __float2bfloat16(v);
    g_wth[i] = h;
    g_wtl[i] = __float2bfloat16(v - __bfloat162float(h));
}

// ---------------- pipelined bf16x3 GEMM, fragment reuse across passes ----------------
__device__ __forceinline__ void issue_chunk(
    uint32_t sb, const __nv_bfloat16* __restrict__ bh, const __nv_bfloat16* __restrict__ bl,
    int row0, int n0, int k0, int tid)
{
#pragma unroll
    for (int i = 0; i < 8; i++) {
        int u = tid + i * 256;
        int buf = u >> 9;
        int rem = u & 511;
        int row = rem >> 2;
        int c8  = (rem & 3) * 8;
        const __nv_bfloat16* src;
        if (buf == 0)      src = g_ah + (size_t)(row0 + row) * DIM + k0 + c8;
        else if (buf == 1) src = g_al + (size_t)(row0 + row) * DIM + k0 + c8;
        else if (buf == 2) src = bh + (size_t)(n0 + row) * DIM + k0 + c8;
        else               src = bl + (size_t)(n0 + row) * DIM + k0 + c8;
        uint32_t dst = sb + buf * 10240 + row * PRB + c8 * 2;
        CP_ASYNC16(dst, src);
    }
    CP_COMMIT();
}

__global__ __launch_bounds__(256, 2) void gemm_mma_kernel(
    int layer, const float* __restrict__ bias,
    float* __restrict__ dout, int out_sel)
{
    extern __shared__ char smem[];
    const uint32_t sbase = smem_u32(smem);
    const int tid = threadIdx.x;
    const int wid = tid >> 5, lane = tid & 31;
    const int z = blockIdx.z;
    const int row0 = blockIdx.x * TM;
    const int n0 = blockIdx.y * TN;
    const int mat = layer * 3 + z;

    float* C = (z == 0)
        ? ((out_sel == 0) ? g_h1 : (out_sel == 1) ? g_h2 : dout)
        : g_xr + (size_t)(z - 1) * N_NODES * DIM;

    const __nv_bfloat16* wth = g_wth + (size_t)mat * DIM * DIM;
    const __nv_bfloat16* wtl = g_wtl + (size_t)mat * DIM * DIM;

    const int wr = (wid >> 1) * 32;
    const int wc = (wid & 1) * 64;
    const int lrow = lane & 15;
    const int lcol8 = (lane >> 4) * 8;

    float acc[64];
#pragma unroll
    for (int i = 0; i < 64; i++) acc[i] = 0.0f;

    issue_chunk(sbase, wth, wtl, row0, n0, 0, tid);

    for (int c = 0; c < NCHUNK; c++) {
        if (c + 1 < NCHUNK) {
            issue_chunk(sbase + ((c + 1) & 1) * STAGE_BYTES, wth, wtl,
                        row0, n0, (c + 1) * KC, tid);
            CP_WAIT1();
        } else {
            CP_WAIT0();
        }
        __syncthreads();

        const uint32_t stg = sbase + (c & 1) * STAGE_BYTES;
#pragma unroll
        for (int ks = 0; ks < 2; ks++) {
            const int kb = (ks * 16 + lcol8) * 2;
            uint32_t ah[2][4], al[2][4], bh4[4][4], bl4[4][4];
#pragma unroll
            for (int mt = 0; mt < 2; mt++) {
                const uint32_t ra = (wr + mt * 16 + lrow) * PRB + kb;
                LDSM_X4(ah[mt], stg + ST_AH + ra);
                LDSM_X4(al[mt], stg + ST_AL + ra);
            }
#pragma unroll
            for (int g = 0; g < 4; g++) {
                const uint32_t rb = (wc + g * 16 + lrow) * PRB + kb;
                LDSM_X4(bh4[g], stg + ST_BH + rb);
                LDSM_X4(bl4[g], stg + ST_BL + rb);
            }
#pragma unroll
            for (int mt = 0; mt < 2; mt++)
#pragma unroll
                for (int g = 0; g < 4; g++) {
                    float* d0 = &acc[((mt * 4 + g) * 2 + 0) * 4];
                    float* d1 = &acc[((mt * 4 + g) * 2 + 1) * 4];
                    mma16816(d0, ah[mt], bh4[g][0], bh4[g][2]);
                    mma16816(d1, ah[mt], bh4[g][1], bh4[g][3]);
                    mma16816(d0, ah[mt], bl4[g][0], bl4[g][2]);
                    mma16816(d1, ah[mt], bl4[g][1], bl4[g][3]);
                    mma16816(d0, al[mt], bh4[g][0], bh4[g][2]);
                    mma16816(d1, al[mt], bh4[g][1], bh4[g][3]);
                }
        }
        __syncthreads();
    }

    // ---- epilogue ----
    const int qr = lane >> 2, qc = (lane & 3) * 2;
#pragma unroll
    for (int mt = 0; mt < 2; mt++) {
#pragma unroll
        for (int nt = 0; nt < 8; nt++) {
            const float* d = &acc[((mt * 4 + (nt >> 1)) * 2 + (nt & 1)) * 4];
            int m0 = row0 + wr + mt * 16 + qr;
            int n = n0 + wc + (nt >> 1) * 16 + (nt & 1) * 8 + qc;
            float bx = 0.f, by = 0.f;
            if (z == 0) {
                float2 bb = *(const float2*)(bias + n);
                bx = bb.x; by = bb.y;
            }
            if (m0 < N_NODES)
                *(float2*)(C + (size_t)m0 * DIM + n) = make_float2(d[0] + bx, d[1] + by);
            if (m0 + 8 < N_NODES)
                *(float2*)(C + (size_t)(m0 + 8) * DIM + n) = make_float2(d[2] + bx, d[3] + by);
        }
    }
}

// ---------------- CSR gather: one 96-thread CTA per dst node ----------------
// out_sel 0/1: h = g_h1/g_h2, write relu'd bf16 split to g_ah/g_al (next layer input)
// out_sel 2:   add aggregation into dout
__global__ __launch_bounds__(96) void gather_kernel(float* __restrict__ dout, int out_sel)
{
    const int d = blockIdx.x;
    const int c = threadIdx.x * 4;
    const int beg = g_off[d], end = g_off[d + 1];

    float4 acc = make_float4(0.f, 0.f, 0.f, 0.f);
    for (int j = beg; j < end; j++) {
        float s = g_pscale[j];
        float4 v = *(const float4*)(g_xr + g_psrc[j] + c);
        acc.x += v.x * s; acc.y += v.y * s; acc.z += v.z * s; acc.w += v.w * s;
    }

    const size_t idx = (size_t)d * DIM + c;
    if (out_sel == 2) {
        float4 r = *(const float4*)(dout + idx);
        r.x += acc.x; r.y += acc.y; r.z += acc.z; r.w += acc.w;
        *(float4*)(dout + idx) = r;
    } else {
        const float* h = (out_sel == 0) ? g_h1 : g_h2;
        float4 r = *(const float4*)(h + idx);
        float f[4] = { fmaxf(r.x + acc.x, 0.f), fmaxf(r.y + acc.y, 0.f),
                       fmaxf(r.z + acc.z, 0.f), fmaxf(r.w + acc.w, 0.f) };
        __nv_bfloat16 hi[4], lo[4];
#pragma unroll
        for (int i = 0; i < 4; i++) {
            hi[i] = __float2bfloat16(f[i]);
            lo[i] = __float2bfloat16(f[i] - __bfloat162float(hi[i]));
        }
        *(uint2*)(g_ah + idx) = *(uint2*)hi;
        *(uint2*)(g_al + idx) = *(uint2*)lo;
    }
}

// ---------------- launch ----------------
extern "C" void kernel_launch(void* const* d_in, const int* in_sizes, int n_in,
                              void* d_out, int out_size)
{
    const float* emb = (const float*)d_in[0];
    const int*   ei  = (const int*)d_in[1];
    const int*   et  = (const int*)d_in[2];
    const float* W1 = (const float*)d_in[3];
    const float* r1 = (const float*)d_in[4];
    const float* b1 = (const float*)d_in[5];
    const float* W2 = (const float*)d_in[6];
    const float* r2 = (const float*)d_in[7];
    const float* b2 = (const float*)d_in[8];
    const float* W3 = (const float*)d_in[9];
    const float* r3 = (const float*)d_in[10];
    const float* b3 = (const float*)d_in[11];
    float* out = (float*)d_out;

    cudaFuncSetAttribute(gemm_mma_kernel,
                         cudaFuncAttributeMaxDynamicSharedMemorySize, SMEM_TOTAL);

    // preprocessing: counts -> CSR offsets -> permuted edge list
    zero_kernel<<<(N_NODES * NREL + 255) / 256, 256>>>();
    count_kernel<<<(N_EDGES + 255) / 256, 256>>>(ei, et);
    scan2_kernel<<<1, 1024>>>();
    permute_kernel<<<(N_EDGES + 255) / 256, 256>>>(ei, et);
    convert_w_kernel<<<(9 * DIM * DIM + 255) / 256, 256>>>(W1, r1, W2, r2, W3, r3);

    dim3 ggrid(MTILES, 3, 3);
    int cv_blocks = (int)(((size_t)N_NODES * DIM + 511) / 512);

    // layer 1
    convert_x_kernel<<<cv_blocks, 512>>>(emb);
    gemm_mma_kernel<<<ggrid, 256, SMEM_TOTAL>>>(0, b1, out, 0);
    gather_kernel<<<N_NODES, 96>>>(out, 0);
    // layer 2
    gemm_mma_kernel<<<ggrid, 256, SMEM_TOTAL>>>(1, b2, out, 1);
    gather_kernel<<<N_NODES, 96>>>(out, 1);
    // layer 3
    gemm_mma_kernel<<<ggrid, 256, SMEM_TOTAL>>>(2, b3, out, 2);
    gather_kernel<<<N_NODES, 96>>>(out, 2);
}

// round 10
// speedup vs baseline: 2.5305x; 1.0123x over previous
#include <cuda_runtime.h>
#include <cuda_bf16.h>
#include <cstdint>

#define N_NODES 50000
#define M_PAD   50048            // 391 * 128
#define N_EDGES 200000
#define DIM     384
#define XD      384              // x cols
#define AGD     768              // agg cols (2 relations)
#define LK      1152             // logical K: [x | agg0 | agg1]
#define NREL    2

#define TM 128
#define TN 128
#define KC 32
#define NCHUNK 36               // LK / KC
#define MTILES 391
#define PRB 80                  // padded row bytes (32 bf16 = 64B + 16B pad)

// per-stage smem layout (bytes)
#define ST_AH 0
#define ST_AL (TM * PRB)
#define ST_BH (2 * TM * PRB)
#define ST_BL (2 * TM * PRB + TN * PRB)
#define STAGE_BYTES (2 * TM * PRB + 2 * TN * PRB)   // 40960
#define SMEM_TOTAL (2 * STAGE_BYTES)                // 81920

// ---------------- device scratch ----------------
// ping-pong x (bf16 hi/lo), separate agg buffer -> no read/write aliasing
__device__ __align__(16) __nv_bfloat16 g_xh[2][(size_t)M_PAD * XD];
__device__ __align__(16) __nv_bfloat16 g_xl[2][(size_t)M_PAD * XD];
__device__ __align__(16) __nv_bfloat16 g_aggh[(size_t)M_PAD * AGD];
__device__ __align__(16) __nv_bfloat16 g_aggl[(size_t)M_PAD * AGD];
// weights, bf16 hi/lo: [layer][n(384)][k(1152)] = [root; W0; W1] stacked along k
__device__ __align__(16) __nv_bfloat16 g_wth[(size_t)3 * DIM * LK];
__device__ __align__(16) __nv_bfloat16 g_wtl[(size_t)3 * DIM * LK];
__device__ int   g_cnt[N_NODES * NREL];
__device__ int   g_cur[N_NODES];
__device__ int   g_off[N_NODES + 1];
__device__ int   g_psrc[N_EDGES];         // src * XD
__device__ float g_pscale[N_EDGES];       // +s rel0, -s rel1

// ---------------- helpers ----------------
__device__ __forceinline__ uint32_t smem_u32(const void* p) {
    uint32_t a;
    asm("{ .reg .u64 t; cvta.to.shared.u64 t, %1; cvt.u32.u64 %0, t; }" : "=r"(a) : "l"(p));
    return a;
}
#define LDSM_X4(r, a)                                                                   \
    asm volatile("ldmatrix.sync.aligned.m8n8.x4.shared.b16 {%0,%1,%2,%3}, [%4];"        \
        : "=r"((r)[0]), "=r"((r)[1]), "=r"((r)[2]), "=r"((r)[3]) : "r"(a))
#define CP_ASYNC16(dst, src) \
    asm volatile("cp.async.cg.shared.global [%0], [%1], 16;" :: "r"(dst), "l"(src))
#define CP_COMMIT()  asm volatile("cp.async.commit_group;" ::: "memory")
#define CP_WAIT1()   asm volatile("cp.async.wait_group 1;" ::: "memory")
#define CP_WAIT0()   asm volatile("cp.async.wait_group 0;" ::: "memory")

__device__ __forceinline__ void mma16816(float* d, const uint32_t* a,
                                         uint32_t b0, uint32_t b1) {
    asm volatile("mma.sync.aligned.m16n8k16.row.col.f32.bf16.bf16.f32 "
        "{%0,%1,%2,%3}, {%4,%5,%6,%7}, {%8,%9}, {%0,%1,%2,%3};"
        : "+f"(d[0]), "+f"(d[1]), "+f"(d[2]), "+f"(d[3])
        : "r"(a[0]), "r"(a[1]), "r"(a[2]), "r"(a[3]), "r"(b0), "r"(b1));
}

__device__ __forceinline__ void store_split2(__nv_bfloat16* ph, __nv_bfloat16* pl,
                                             float x, float y) {
    __nv_bfloat16 hx = __float2bfloat16(x), hy = __float2bfloat16(y);
    __nv_bfloat16 lx = __float2bfloat16(x - __bfloat162float(hx));
    __nv_bfloat16 ly = __float2bfloat16(y - __bfloat162float(hy));
    __nv_bfloat162 H; H.x = hx; H.y = hy;
    __nv_bfloat162 L; L.x = lx; L.y = ly;
    *(__nv_bfloat162*)ph = H;
    *(__nv_bfloat162*)pl = L;
}

// ---------------- edge preprocessing ----------------
__global__ void zero_kernel() {
    int i = blockIdx.x * blockDim.x + threadIdx.x;
    if (i < N_NODES * NREL) g_cnt[i] = 0;
    if (i < N_NODES) g_cur[i] = 0;
}
__device__ __forceinline__ int clampi(int v, int hi) {
    v = v < 0 ? 0 : v;
    return v >= hi ? hi - 1 : v;
}
__global__ void count_kernel(const int* __restrict__ ei, const int* __restrict__ et) {
    int e = blockIdx.x * blockDim.x + threadIdx.x;
    if (e >= N_EDGES) return;
    atomicAdd(&g_cnt[clampi(ei[N_EDGES + e], N_NODES) * NREL + clampi(et[e], NREL)], 1);
}

__global__ void scan2_kernel() {
    __shared__ int wsum[32];
    __shared__ int s_carry;
    const int tid = threadIdx.x;
    const int lane = tid & 31, w = tid >> 5;
    if (tid == 0) s_carry = 0;
    __syncthreads();
    for (int base = 0; base < N_NODES; base += 1024) {
        int i = base + tid;
        int v = (i < N_NODES) ? (g_cnt[i * NREL] + g_cnt[i * NREL + 1]) : 0;
        int incl = v;
#pragma unroll
        for (int o = 1; o < 32; o <<= 1) {
            int n = __shfl_up_sync(0xFFFFFFFF, incl, o);
            if (lane >= o) incl += n;
        }
        if (lane == 31) wsum[w] = incl;
        __syncthreads();
        if (w == 0) {
            int s = wsum[lane];
#pragma unroll
            for (int o = 1; o < 32; o <<= 1) {
                int n = __shfl_up_sync(0xFFFFFFFF, s, o);
                if (lane >= o) s += n;
            }
            wsum[lane] = s;
        }
        __syncthreads();
        int blk_excl = incl - v + (w > 0 ? wsum[w - 1] : 0);
        if (i < N_NODES) g_off[i] = s_carry + blk_excl;
        __syncthreads();
        if (tid == 0) s_carry += wsum[31];
        __syncthreads();
    }
    if (tid == 0) g_off[N_NODES] = s_carry;
}

__global__ void permute_kernel(const int* __restrict__ ei, const int* __restrict__ et) {
    int e = blockIdx.x * blockDim.x + threadIdx.x;
    if (e >= N_EDGES) return;
    int src = clampi(ei[e], N_NODES);
    int dst = clampi(ei[N_EDGES + e], N_NODES);
    int r   = clampi(et[e], NREL);
    int slot = g_off[dst] + atomicAdd(&g_cur[dst], 1);
    g_psrc[slot] = src * XD;
    int c = g_cnt[dst * NREL + r];
    float s = 1.0f / (float)(c > 0 ? c : 1);
    g_pscale[slot] = (r == 0) ? s : -s;
}

// ---------------- input split (layer 1): emb -> x buffer 0 ----------------
__global__ void convert_x_kernel(const float* __restrict__ ext) {
    size_t i = (size_t)blockIdx.x * blockDim.x + threadIdx.x;
    if (i >= (size_t)N_NODES * XD) return;
    float v = ext[i];
    __nv_bfloat16 h = __float2bfloat16(v);
    g_xh[0][i] = h;
    g_xl[0][i] = __float2bfloat16(v - __bfloat162float(h));
}

// ---------------- weight build ----------------
__global__ void convert_w_kernel(const float* __restrict__ W1, const float* __restrict__ r1,
                                 const float* __restrict__ W2, const float* __restrict__ r2,
                                 const float* __restrict__ W3, const float* __restrict__ r3) {
    size_t i = (size_t)blockIdx.x * blockDim.x + threadIdx.x;
    if (i >= (size_t)3 * DIM * LK) return;
    int L = (int)(i / (DIM * LK));
    int rem = (int)(i % (DIM * LK));
    int n = rem / LK, k = rem % LK;
    const float* root = (L == 0) ? r1 : (L == 1) ? r2 : r3;
    const float* Wr   = (L == 0) ? W1 : (L == 1) ? W2 : W3;
    float v;
    if (k < DIM) v = root[(size_t)k * DIM + n];
    else {
        int r = (k - DIM) / DIM, kk = (k - DIM) % DIM;
        v = Wr[(size_t)r * DIM * DIM + (size_t)kk * DIM + n];
    }
    __nv_bfloat16 h = __float2bfloat16(v);
    g_wth[i] = h;
    g_wtl[i] = __float2bfloat16(v - __bfloat162float(h));
}

// ---------------- CSR gather: agg from x[xsel] -> g_agg ----------------
__global__ __launch_bounds__(96) void gather_kernel(int xsel)
{
    const int d = blockIdx.x;
    const int c = threadIdx.x * 4;
    const int beg = g_off[d], end = g_off[d + 1];
    const __nv_bfloat16* xh = g_xh[xsel];
    const __nv_bfloat16* xl = g_xl[xsel];

    float4 a0 = make_float4(0.f, 0.f, 0.f, 0.f);
    float4 a1 = make_float4(0.f, 0.f, 0.f, 0.f);
    for (int j = beg; j < end; j++) {
        float s = g_pscale[j];
        int off = g_psrc[j] + c;
        uint2 hu = *(const uint2*)(xh + off);
        uint2 lu = *(const uint2*)(xl + off);
        __nv_bfloat162 h01 = *(__nv_bfloat162*)&hu.x;
        __nv_bfloat162 h23 = *(__nv_bfloat162*)&hu.y;
        __nv_bfloat162 l01 = *(__nv_bfloat162*)&lu.x;
        __nv_bfloat162 l23 = *(__nv_bfloat162*)&lu.y;
        float4 v;
        v.x = __bfloat162float(h01.x) + __bfloat162float(l01.x);
        v.y = __bfloat162float(h01.y) + __bfloat162float(l01.y);
        v.z = __bfloat162float(h23.x) + __bfloat162float(l23.x);
        v.w = __bfloat162float(h23.y) + __bfloat162float(l23.y);
        if (s > 0.f) {
            a0.x += s * v.x; a0.y += s * v.y; a0.z += s * v.z; a0.w += s * v.w;
        } else {
            a1.x -= s * v.x; a1.y -= s * v.y; a1.z -= s * v.z; a1.w -= s * v.w;
        }
    }

    const size_t base = (size_t)d * AGD;
    store_split2(g_aggh + base + c,           g_aggl + base + c,           a0.x, a0.y);
    store_split2(g_aggh + base + c + 2,       g_aggl + base + c + 2,       a0.z, a0.w);
    store_split2(g_aggh + base + XD + c,      g_aggl + base + XD + c,      a1.x, a1.y);
    store_split2(g_aggh + base + XD + c + 2,  g_aggl + base + XD + c + 2,  a1.z, a1.w);
}

// ---------------- pipelined bf16x3 GEMM over logical K=1152, grid (MTILES, 3) ----------------
__device__ __forceinline__ void issue_chunk(
    uint32_t sb, int xsel,
    const __nv_bfloat16* __restrict__ bh, const __nv_bfloat16* __restrict__ bl,
    int row0, int n0, int k0, int tid)
{
    const bool in_x = (k0 < XD);
    const __nv_bfloat16* ah = in_x ? g_xh[xsel] : g_aggh;
    const __nv_bfloat16* al = in_x ? g_xl[xsel] : g_aggl;
    const int astride = in_x ? XD : AGD;
    const int ak0 = in_x ? k0 : k0 - XD;
#pragma unroll
    for (int i = 0; i < 8; i++) {
        int u = tid + i * 256;
        int buf = u >> 9;
        int rem = u & 511;
        int row = rem >> 2;
        int c8  = (rem & 3) * 8;
        const __nv_bfloat16* src;
        if (buf == 0)      src = ah + (size_t)(row0 + row) * astride + ak0 + c8;
        else if (buf == 1) src = al + (size_t)(row0 + row) * astride + ak0 + c8;
        else if (buf == 2) src = bh + (size_t)(n0 + row) * LK + k0 + c8;
        else               src = bl + (size_t)(n0 + row) * LK + k0 + c8;
        uint32_t dst = sb + buf * 10240 + row * PRB + c8 * 2;
        CP_ASYNC16(dst, src);
    }
    CP_COMMIT();
}

__global__ __launch_bounds__(256, 2) void gemm_mma_kernel(
    int layer, int xsel, const float* __restrict__ bias,
    float* __restrict__ dout, int last)
{
    extern __shared__ char smem[];
    const uint32_t sbase = smem_u32(smem);
    const int tid = threadIdx.x;
    const int wid = tid >> 5, lane = tid & 31;
    const int row0 = blockIdx.x * TM;
    const int n0 = blockIdx.y * TN;

    const __nv_bfloat16* wth = g_wth + (size_t)layer * DIM * LK;
    const __nv_bfloat16* wtl = g_wtl + (size_t)layer * DIM * LK;

    const int wr = (wid >> 1) * 32;
    const int wc = (wid & 1) * 64;
    const int lrow = lane & 15;
    const int lcol8 = (lane >> 4) * 8;

    float acc[64];
#pragma unroll
    for (int i = 0; i < 64; i++) acc[i] = 0.0f;

    issue_chunk(sbase, xsel, wth, wtl, row0, n0, 0, tid);

    for (int c = 0; c < NCHUNK; c++) {
        if (c + 1 < NCHUNK) {
            issue_chunk(sbase + ((c + 1) & 1) * STAGE_BYTES, xsel, wth, wtl,
                        row0, n0, (c + 1) * KC, tid);
            CP_WAIT1();
        } else {
            CP_WAIT0();
        }
        __syncthreads();

        const uint32_t stg = sbase + (c & 1) * STAGE_BYTES;
#pragma unroll
        for (int ks = 0; ks < 2; ks++) {
            const int kb = (ks * 16 + lcol8) * 2;
            uint32_t ah[2][4], al[2][4], bh4[4][4], bl4[4][4];
#pragma unroll
            for (int mt = 0; mt < 2; mt++) {
                const uint32_t ra = (wr + mt * 16 + lrow) * PRB + kb;
                LDSM_X4(ah[mt], stg + ST_AH + ra);
                LDSM_X4(al[mt], stg + ST_AL + ra);
            }
#pragma unroll
            for (int g = 0; g < 4; g++) {
                const uint32_t rb = (wc + g * 16 + lrow) * PRB + kb;
                LDSM_X4(bh4[g], stg + ST_BH + rb);
                LDSM_X4(bl4[g], stg + ST_BL + rb);
            }
#pragma unroll
            for (int mt = 0; mt < 2; mt++)
#pragma unroll
                for (int g = 0; g < 4; g++) {
                    float* d0 = &acc[((mt * 4 + g) * 2 + 0) * 4];
                    float* d1 = &acc[((mt * 4 + g) * 2 + 1) * 4];
                    mma16816(d0, ah[mt], bh4[g][0], bh4[g][2]);
                    mma16816(d1, ah[mt], bh4[g][1], bh4[g][3]);
                    mma16816(d0, ah[mt], bl4[g][0], bl4[g][2]);
                    mma16816(d1, ah[mt], bl4[g][1], bl4[g][3]);
                    mma16816(d0, al[mt], bh4[g][0], bh4[g][2]);
                    mma16816(d1, al[mt], bh4[g][1], bh4[g][3]);
                }
        }
        __syncthreads();
    }

    // ---- epilogue: +bias; non-last: relu + split into x[xsel^1]; last: fp32 dout ----
    const int qr = lane >> 2, qc = (lane & 3) * 2;
    __nv_bfloat16* oxh = g_xh[xsel ^ 1];
    __nv_bfloat16* oxl = g_xl[xsel ^ 1];
#pragma unroll
    for (int mt = 0; mt < 2; mt++) {
#pragma unroll
        for (int nt = 0; nt < 8; nt++) {
            const float* d = &acc[((mt * 4 + (nt >> 1)) * 2 + (nt & 1)) * 4];
            int m0 = row0 + wr + mt * 16 + qr;
            int n = n0 + wc + (nt >> 1) * 16 + (nt & 1) * 8 + qc;
            float2 bb = *(const float2*)(bias + n);
#pragma unroll
            for (int h = 0; h < 2; h++) {
                int m = m0 + h * 8;
                if (m >= N_NODES) continue;
                float x = d[h * 2 + 0] + bb.x;
                float y = d[h * 2 + 1] + bb.y;
                if (last) {
                    *(float2*)(dout + (size_t)m * DIM + n) = make_float2(x, y);
                } else {
                    x = fmaxf(x, 0.f); y = fmaxf(y, 0.f);
                    size_t o = (size_t)m * XD + n;
                    store_split2(oxh + o, oxl + o, x, y);
                }
            }
        }
    }
}

// ---------------- launch ----------------
extern "C" void kernel_launch(void* const* d_in, const int* in_sizes, int n_in,
                              void* d_out, int out_size)
{
    const float* emb = (const float*)d_in[0];
    const int*   ei  = (const int*)d_in[1];
    const int*   et  = (const int*)d_in[2];
    const float* W1 = (const float*)d_in[3];
    const float* r1 = (const float*)d_in[4];
    const float* b1 = (const float*)d_in[5];
    const float* W2 = (const float*)d_in[6];
    const float* r2 = (const float*)d_in[7];
    const float* b2 = (const float*)d_in[8];
    const float* W3 = (const float*)d_in[9];
    const float* r3 = (const float*)d_in[10];
    const float* b3 = (const float*)d_in[11];
    float* out = (float*)d_out;

    cudaFuncSetAttribute(gemm_mma_kernel,
                         cudaFuncAttributeMaxDynamicSharedMemorySize, SMEM_TOTAL);

    zero_kernel<<<(N_NODES * NREL + 255) / 256, 256>>>();
    count_kernel<<<(N_EDGES + 255) / 256, 256>>>(ei, et);
    scan2_kernel<<<1, 1024>>>();
    permute_kernel<<<(N_EDGES + 255) / 256, 256>>>(ei, et);
    convert_w_kernel<<<(int)(((size_t)3 * DIM * LK + 255) / 256), 256>>>(W1, r1, W2, r2, W3, r3);

    dim3 ggrid(MTILES, 3);
    int cv_blocks = (int)(((size_t)N_NODES * XD + 511) / 512);

    convert_x_kernel<<<cv_blocks, 512>>>(emb);
    // layer 1: x[0] -> x[1]
    gather_kernel<<<N_NODES, 96>>>(0);
    gemm_mma_kernel<<<ggrid, 256, SMEM_TOTAL>>>(0, 0, b1, out, 0);
    // layer 2: x[1] -> x[0]
    gather_kernel<<<N_NODES, 96>>>(1);
    gemm_mma_kernel<<<ggrid, 256, SMEM_TOTAL>>>(1, 1, b2, out, 0);
    // layer 3: x[0] -> dout
    gather_kernel<<<N_NODES, 96>>>(0);
    gemm_mma_kernel<<<ggrid, 256, SMEM_TOTAL>>>(2, 0, b3, out, 1);
}